// round 1
// baseline (speedup 1.0000x reference)
#include <cuda_runtime.h>
#include <math.h>

#define N_NODES 5000
#define NBINS 50
#define BINSZ 100
#define KNN 16
#define SLOPE 0.01f

// ---------------- device scratch (no allocations allowed) ----------------
__device__ float g_h[N_NODES * 12];     // nn1 output (pre-leaky)
__device__ int   g_bin[N_NODES];
__device__ int   g_hist[NBINS];
__device__ int   g_sorted[N_NODES];     // bins_split flattened
__device__ float g_hf[N_NODES * 32];    // post-conv, post-leaky features

__device__ __forceinline__ float lrelu(float v) { return v > 0.f ? v : SLOPE * v; }

// ---------------- generic 3-layer MLP (IN -> 125 -> 125 -> OUT) ----------
// Block: 256 threads = 32 rows x 8 threads/row. Each thread computes a
// 16-wide output chunk per hidden layer. Weights staged in padded smem
// ([k][128] pitch) so inner loads vectorize to LDS.128.
template <int IN1, int IN2, int OUT>
__global__ void mlp_kernel(const float* __restrict__ xa, const float* __restrict__ xb,
                           const float* __restrict__ W1, const float* __restrict__ b1,
                           const float* __restrict__ W2, const float* __restrict__ b2,
                           const float* __restrict__ W3, const float* __restrict__ b3,
                           float* __restrict__ out, int zero_hist)
{
    constexpr int IN = IN1 + IN2;
    extern __shared__ float sm[];
    float* Ws1 = sm;                       // IN*128
    float* Ws2 = Ws1 + IN * 128;           // 125*128
    float* Ws3 = Ws2 + 125 * 128;          // 125*16
    float* b1s = Ws3 + 125 * 16;           // 128
    float* b2s = b1s + 128;                // 128
    float* b3s = b2s + 128;                // 16
    float* h1s = b3s + 16;                 // 32*133
    float* h2s = h1s + 32 * 133;           // 32*133

    const int tid = threadIdx.x;
    if (zero_hist && blockIdx.x == 0 && tid < NBINS) g_hist[tid] = 0;

    for (int idx = tid; idx < IN * 125; idx += 256) {
        int k = idx / 125, j = idx % 125;
        Ws1[k * 128 + j] = W1[idx];
    }
    for (int idx = tid; idx < 125 * 125; idx += 256) {
        int k = idx / 125, j = idx % 125;
        Ws2[k * 128 + j] = W2[idx];
    }
    for (int idx = tid; idx < 125 * OUT; idx += 256) {
        int k = idx / OUT, o = idx % OUT;
        Ws3[k * 16 + o] = W3[idx];
    }
    if (tid < 125) { b1s[tid] = b1[tid]; b2s[tid] = b2[tid]; }
    if (tid < OUT) b3s[tid] = b3[tid];
    __syncthreads();

    const int lr = tid >> 3;   // local row 0..31
    const int t  = tid & 7;    // thread-in-row
    const int j0 = t * 16;
    const int ntiles = (N_NODES + 31) / 32;

    for (int tile = blockIdx.x; tile < ntiles; tile += gridDim.x) {
        const int row = tile * 32 + lr;
        const bool valid = row < N_NODES;

        float xin[IN];
        if (valid) {
            #pragma unroll
            for (int k = 0; k < IN1; k++) xin[k] = xa[row * IN1 + k];
            #pragma unroll
            for (int k = 0; k < IN2; k++) xin[IN1 + k] = xb[row * IN2 + k];
        } else {
            #pragma unroll
            for (int k = 0; k < IN; k++) xin[k] = 0.f;
        }

        float acc[16];
        // ---- layer 1 ----
        #pragma unroll
        for (int jj = 0; jj < 16; jj++) acc[jj] = (j0 + jj < 125) ? b1s[j0 + jj] : 0.f;
        #pragma unroll
        for (int k = 0; k < IN; k++) {
            const float xv = xin[k];
            #pragma unroll
            for (int jj = 0; jj < 16; jj++) acc[jj] += xv * Ws1[k * 128 + j0 + jj];
        }
        #pragma unroll
        for (int jj = 0; jj < 16; jj++) {
            const int j = j0 + jj;
            if (j < 125) h1s[lr * 133 + j] = lrelu(acc[jj]);
        }
        __syncthreads();

        // ---- layer 2 ----
        #pragma unroll
        for (int jj = 0; jj < 16; jj++) acc[jj] = (j0 + jj < 125) ? b2s[j0 + jj] : 0.f;
        #pragma unroll 5
        for (int k = 0; k < 125; k++) {
            const float hv = h1s[lr * 133 + k];
            #pragma unroll
            for (int jj = 0; jj < 16; jj++) acc[jj] += hv * Ws2[k * 128 + j0 + jj];
        }
        #pragma unroll
        for (int jj = 0; jj < 16; jj++) {
            const int j = j0 + jj;
            if (j < 125) h2s[lr * 133 + j] = lrelu(acc[jj]);
        }
        __syncthreads();

        // ---- layer 3 (no activation) ----
        if (valid) {
            for (int o = t; o < OUT; o += 8) {
                float a = b3s[o];
                #pragma unroll 5
                for (int k = 0; k < 125; k++) a += h2s[lr * 133 + k] * Ws3[k * 16 + o];
                out[row * OUT + o] = a;
            }
        }
        __syncthreads();
    }
}

// ---------------- bin index: argmax over [h@cb, -(h@cb)] ------------------
__global__ void binidx_kernel(const float* __restrict__ cb)
{
    __shared__ int hloc[NBINS];
    __shared__ float cbs[12 * 25];
    const int tid = threadIdx.x;
    if (tid < NBINS) hloc[tid] = 0;
    for (int idx = tid; idx < 12 * 25; idx += blockDim.x) {
        int k = idx / 25, c = idx % 25;
        cbs[idx] = cb[k * 100 + c];
    }
    __syncthreads();

    const int n = blockIdx.x * blockDim.x + tid;
    if (n < N_NODES) {
        float hr[12];
        #pragma unroll
        for (int k = 0; k < 12; k++) hr[k] = g_h[n * 12 + k];
        float mul[25];
        #pragma unroll
        for (int c = 0; c < 25; c++) {
            float s = 0.f;
            #pragma unroll
            for (int k = 0; k < 12; k++) s += hr[k] * cbs[k * 25 + c];
            mul[c] = s;
        }
        float best = -3.4e38f; int bi = 0;
        #pragma unroll
        for (int c = 0; c < 50; c++) {
            const float v = (c < 25) ? mul[c] : -mul[c - 25];
            if (v > best) { best = v; bi = c; }   // strict > : first max (jnp.argmax)
        }
        g_bin[n] = bi;
        atomicAdd(&hloc[bi], 1);
    }
    __syncthreads();
    if (tid < NBINS && hloc[tid] > 0) atomicAdd(&g_hist[tid], hloc[tid]);
}

// ---------------- stable counting-sort scatter (1 warp per bin) -----------
__global__ void sort_kernel()
{
    const int b = blockIdx.x;
    const int lane = threadIdx.x;
    int off = 0;
    for (int i = 0; i < b; i++) off += g_hist[i];
    for (int base = 0; base < N_NODES; base += 32) {
        const int i = base + lane;
        const bool p = (i < N_NODES) && (g_bin[i] == b);
        const unsigned m = __ballot_sync(0xffffffffu, p);
        if (p) {
            const int pos = off + __popc(m & ((1u << lane) - 1u));
            g_sorted[pos] = i;
        }
        off += __popc(m);
    }
}

// ---------------- per-bin: similarity, top-16, GCNConv, GraphConv ---------
__global__ void bin_kernel(const float* __restrict__ gcnW, const float* __restrict__ gcnb,
                           const float* __restrict__ Wrel, const float* __restrict__ brel,
                           const float* __restrict__ Wroot)
{
    extern __shared__ float sm[];
    float* P    = sm;                    // 100 x 13 (pitch 13), h then leaky(h)
    float* D    = P + 100 * 13;          // 100 x 101 sigmoid similarity
    float* HW   = D + 100 * 101;         // 100 x 33  leaky(h) @ gcnW
    float* GC   = HW + 100 * 33;         // 100 x 33  GCN output
    float* AGG  = GC + 100 * 33;         // 100 x 33  GraphConv aggregate
    float* Ew   = AGG + 100 * 33;        // 1600 edge weights (sorted desc per row)
    float* coef = Ew + 1600;             // 1600 ew*dis[src]
    float* degf = coef + 1600;           // 100  -> dis
    int* sids  = (int*)(degf + 100);     // 100
    int* Ed    = sids + 100;             // 1600 local dst
    int* roff  = Ed + 1600;              // 104 CSR offsets
    int* cnt   = roff + 104;             // 100
    int* rlist = cnt + 100;              // 1600 reverse edge list

    const int tid = threadIdx.x;
    const int b = blockIdx.x;

    if (tid < 100) sids[tid] = g_sorted[b * 100 + tid];
    __syncthreads();
    for (int idx = tid; idx < 1200; idx += 256) {
        const int i = idx / 12, k = idx % 12;
        P[i * 13 + k] = g_h[sids[i] * 12 + k];
    }
    __syncthreads();

    // sigmoid similarity (symmetric)
    for (int p = tid; p < 10000; p += 256) {
        const int i = p / 100, j = p % 100;
        if (j < i) continue;
        float s = 0.f;
        #pragma unroll
        for (int k = 0; k < 12; k++) s += P[i * 13 + k] * P[j * 13 + k];
        const float v = 1.f / (1.f + expf(-s));
        D[i * 101 + j] = v;
        D[j * 101 + i] = v;
    }
    __syncthreads();

    // top-16 per row: selection with JAX tie rule (equal -> lower index first)
    if (tid < 100) {
        const int i = tid;
        for (int kk = 0; kk < KNN; kk++) {
            float bv = -1.f; int bj = 0;
            for (int j = 0; j < 100; j++) {
                const float v = D[i * 101 + j];
                if (v > bv) { bv = v; bj = j; }
            }
            D[i * 101 + bj] = -2.f;
            Ew[i * 16 + kk] = bv;
            Ed[i * 16 + kk] = bj;
        }
    }
    if (tid < 104) roff[tid] = 0;
    if (tid < 100) cnt[tid] = 0;
    __syncthreads();

    // reverse CSR
    for (int e = tid; e < 1600; e += 256) atomicAdd(&roff[Ed[e] + 1], 1);
    __syncthreads();
    if (tid == 0) {
        for (int c = 0; c < 100; c++) roff[c + 1] += roff[c];
    }
    __syncthreads();
    for (int e = tid; e < 1600; e += 256) {
        const int d = Ed[e];
        const int slot = atomicAdd(&cnt[d], 1);
        rlist[roff[d] + slot] = e;
    }
    __syncthreads();

    // degree (self loop weight 1 + incoming ew) -> dis
    if (tid < 100) {
        float dg = 1.f;
        for (int q = roff[tid]; q < roff[tid + 1]; q++) dg += Ew[rlist[q]];
        degf[tid] = 1.f / sqrtf(dg);
    }
    __syncthreads();

    // leaky in place (only k<12 columns used downstream)
    for (int idx = tid; idx < 1300; idx += 256) P[idx] = lrelu(P[idx]);
    __syncthreads();

    for (int e = tid; e < 1600; e += 256) coef[e] = Ew[e] * degf[e >> 4];

    // HW = leaky(h) @ gcnW  (thread owns output column f)
    {
        const int f = tid & 31;
        float wcol[12];
        #pragma unroll
        for (int k = 0; k < 12; k++) wcol[k] = gcnW[k * 32 + f];
        for (int c = tid >> 5; c < 100; c += 8) {
            float a = 0.f;
            #pragma unroll
            for (int k = 0; k < 12; k++) a += P[c * 13 + k] * wcol[k];
            HW[c * 33 + f] = a;
        }
    }
    __syncthreads();

    // GCNConv: gather over incoming edges + normalized self loop
    {
        const int f = tid & 31;
        const float bias = gcnb[f];
        for (int c = tid >> 5; c < 100; c += 8) {
            float a = 0.f;
            const int q1 = roff[c + 1];
            for (int q = roff[c]; q < q1; q++) {
                const int e = rlist[q];
                a += coef[e] * HW[(e >> 4) * 33 + f];
            }
            const float dc = degf[c];
            GC[c * 33 + f] = bias + dc * a + dc * dc * HW[c * 33 + f];
        }
    }
    __syncthreads();

    // GraphConv aggregate: sum ew * GC[src]
    {
        const int f = tid & 31;
        for (int c = tid >> 5; c < 100; c += 8) {
            float a = 0.f;
            const int q1 = roff[c + 1];
            for (int q = roff[c]; q < q1; q++) {
                const int e = rlist[q];
                a += Ew[e] * GC[(e >> 4) * 33 + f];
            }
            AGG[c * 33 + f] = a;
        }
    }
    __syncthreads();

    // final: AGG @ Wrel + brel + GC @ Wroot, leaky, scatter to global
    {
        const int f = tid & 31;
        float wr[32], wt[32];
        #pragma unroll
        for (int k = 0; k < 32; k++) { wr[k] = Wrel[k * 32 + f]; wt[k] = Wroot[k * 32 + f]; }
        const float bb = brel[f];
        for (int c = tid >> 5; c < 100; c += 8) {
            float a = bb;
            #pragma unroll
            for (int k = 0; k < 32; k++) a += AGG[c * 33 + k] * wr[k] + GC[c * 33 + k] * wt[k];
            g_hf[sids[c] * 32 + f] = lrelu(a);
        }
    }
}

// ---------------- host launcher ------------------------------------------
static constexpr size_t mlp_smem_bytes(int IN) {
    return (size_t)(IN * 128 + 125 * 128 + 125 * 16 + 128 + 128 + 16 + 2 * 32 * 133) * 4;
}
static constexpr size_t bin_smem_bytes() {
    size_t f = 100 * 13 + 100 * 101 + 3 * (100 * 33) + 1600 + 1600 + 100;
    size_t i = 100 + 1600 + 104 + 100 + 1600;
    return (f + i) * 4;
}

extern "C" void kernel_launch(void* const* d_in, const int* in_sizes, int n_in,
                              void* d_out, int out_size)
{
    const float* x       = (const float*)d_in[0];
    const float* ygen_id = (const float*)d_in[1];
    const float* ygen    = (const float*)d_in[2];
    const float* cb      = (const float*)d_in[3];
    const float* nn1_W1 = (const float*)d_in[4];
    const float* nn1_b1 = (const float*)d_in[5];
    const float* nn1_W2 = (const float*)d_in[6];
    const float* nn1_b2 = (const float*)d_in[7];
    const float* nn1_W3 = (const float*)d_in[8];
    const float* nn1_b3 = (const float*)d_in[9];
    const float* gcn_W  = (const float*)d_in[10];
    const float* gcn_b  = (const float*)d_in[11];
    const float* gc_Wrel  = (const float*)d_in[12];
    const float* gc_brel  = (const float*)d_in[13];
    const float* gc_Wroot = (const float*)d_in[14];
    const float* nn2_W1 = (const float*)d_in[15];
    const float* nn2_b1 = (const float*)d_in[16];
    const float* nn2_W2 = (const float*)d_in[17];
    const float* nn2_b2 = (const float*)d_in[18];
    const float* nn2_W3 = (const float*)d_in[19];
    const float* nn2_b3 = (const float*)d_in[20];
    const float* nn3_W1 = (const float*)d_in[21];
    const float* nn3_b1 = (const float*)d_in[22];
    const float* nn3_W2 = (const float*)d_in[23];
    const float* nn3_b2 = (const float*)d_in[24];
    const float* nn3_W3 = (const float*)d_in[25];
    const float* nn3_b3 = (const float*)d_in[26];

    float* out = (float*)d_out;
    float* cand_ids = out;               // [5000,6]
    float* cand_p4  = out + 30000;       // [5000,6]

    void *ph, *phf;
    cudaGetSymbolAddress(&ph, g_h);
    cudaGetSymbolAddress(&phf, g_hf);
    float* h_ptr  = (float*)ph;
    float* hf_ptr = (float*)phf;

    cudaFuncSetAttribute(mlp_kernel<12, 0, 12>, cudaFuncAttributeMaxDynamicSharedMemorySize, (int)mlp_smem_bytes(12));
    cudaFuncSetAttribute(mlp_kernel<32, 0, 6>,  cudaFuncAttributeMaxDynamicSharedMemorySize, (int)mlp_smem_bytes(32));
    cudaFuncSetAttribute(mlp_kernel<32, 6, 6>,  cudaFuncAttributeMaxDynamicSharedMemorySize, (int)mlp_smem_bytes(38));
    cudaFuncSetAttribute(bin_kernel, cudaFuncAttributeMaxDynamicSharedMemorySize, (int)bin_smem_bytes());

    // nn1 (also zeros the bin histogram from block 0)
    mlp_kernel<12, 0, 12><<<148, 256, mlp_smem_bytes(12)>>>(
        x, nullptr, nn1_W1, nn1_b1, nn1_W2, nn1_b2, nn1_W3, nn1_b3, h_ptr, 1);

    // passthrough outputs (overlap with compute)
    cudaMemcpyAsync(out + 60000, ygen_id, 30000 * sizeof(float), cudaMemcpyDeviceToDevice);
    cudaMemcpyAsync(out + 90000, ygen,    30000 * sizeof(float), cudaMemcpyDeviceToDevice);

    binidx_kernel<<<(N_NODES + 255) / 256, 256>>>(cb);
    sort_kernel<<<NBINS, 32>>>();
    bin_kernel<<<NBINS, 256, bin_smem_bytes()>>>(gcn_W, gcn_b, gc_Wrel, gc_brel, gc_Wroot);

    mlp_kernel<32, 0, 6><<<148, 256, mlp_smem_bytes(32)>>>(
        hf_ptr, nullptr, nn2_W1, nn2_b1, nn2_W2, nn2_b2, nn2_W3, nn2_b3, cand_ids, 0);
    mlp_kernel<32, 6, 6><<<148, 256, mlp_smem_bytes(38)>>>(
        hf_ptr, cand_ids, nn3_W1, nn3_b1, nn3_W2, nn3_b2, nn3_W3, nn3_b3, cand_p4, 0);
}

// round 2
// speedup vs baseline: 2.4637x; 2.4637x over previous
#include <cuda_runtime.h>
#include <math.h>

#define N_NODES 5000
#define NBINS 50
#define KNN 16
#define SLOPE 0.01f

// ---------------- device scratch ----------------
__device__ float g_h[N_NODES * 12];     // nn1 output (pre-leaky)
__device__ int   g_bin[N_NODES];
__device__ int   g_sorted[N_NODES];     // stable argsort of g_bin
__device__ float g_hf[N_NODES * 32];    // post-conv, post-leaky features

__device__ __forceinline__ float lrelu(float v) { return v > 0.f ? v : SLOPE * v; }

__device__ __forceinline__ unsigned long long pack2(float a, float b) {
    unsigned long long r;
    asm("mov.b64 %0, {%1, %2};" : "=l"(r) : "r"(__float_as_uint(a)), "r"(__float_as_uint(b)));
    return r;
}
__device__ __forceinline__ void unpack2(unsigned long long p, float& a, float& b) {
    unsigned int x, y;
    asm("mov.b64 {%0, %1}, %2;" : "=r"(x), "=r"(y) : "l"(p));
    a = __uint_as_float(x); b = __uint_as_float(y);
}
// packed f32x2 FMA: d = a*b + c on two lanes (bitwise-identical to two scalar FFMAs)
__device__ __forceinline__ unsigned long long ffma2(unsigned long long a, unsigned long long b, unsigned long long c) {
    unsigned long long d;
    asm("fma.rn.f32x2 %0, %1, %2, %3;" : "=l"(d) : "l"(a), "l"(b), "l"(c));
    return d;
}

// ---------------- 3-layer MLP (IN -> 125 -> 125 -> OUT), optional fused LSH bin ----
// Thread map: warp = 16-col group (broadcast weight loads), lane = row (0..31).
// One 32-row tile per block, grid = 157.
template <int IN1, int IN2, int OUT, bool DOBIN>
__global__ __launch_bounds__(256, 1)
void mlp_kernel(const float* __restrict__ xa, const float* __restrict__ xb,
                const float* __restrict__ W1, const float* __restrict__ b1,
                const float* __restrict__ W2, const float* __restrict__ b2,
                const float* __restrict__ W3, const float* __restrict__ b3,
                float* __restrict__ out, const float* __restrict__ cb,
                const float* __restrict__ csrc, float* __restrict__ cdst, int ncopy)
{
    constexpr int IN = IN1 + IN2;
    extern __shared__ float sm[];
    float* Ws1 = sm;                      // IN*128 (cols 125..127 zeroed)
    float* Ws2 = Ws1 + IN * 128;          // 125*128
    float* Ws3 = Ws2 + 125 * 128;         // 125*16
    float* b1s = Ws3 + 125 * 16;          // 128
    float* b2s = b1s + 128;               // 128
    float* b3s = b2s + 128;               // 16
    float* h1s = b3s + 16;                // 32*133
    float* h2s = h1s + 32 * 133;          // 32*133
    float* cbs = h2s + 32 * 133;          // 300 (DOBIN only)

    const int tid = threadIdx.x;

    // fused passthrough copy (ygen / ygen_id)
    if (csrc != nullptr) {
        const int i = blockIdx.x * 256 + tid;
        if (i < ncopy) cdst[i] = csrc[i];
    }

    for (int idx = tid; idx < IN * 128; idx += 256) {
        const int k = idx >> 7, j = idx & 127;
        Ws1[idx] = (j < 125) ? W1[k * 125 + j] : 0.f;
    }
    for (int idx = tid; idx < 125 * 128; idx += 256) {
        const int k = idx >> 7, j = idx & 127;
        Ws2[idx] = (j < 125) ? W2[k * 125 + j] : 0.f;
    }
    for (int idx = tid; idx < 125 * 16; idx += 256) {
        const int k = idx >> 4, o = idx & 15;
        Ws3[idx] = (o < OUT) ? W3[k * OUT + o] : 0.f;
    }
    if (tid < 128) {
        b1s[tid] = (tid < 125) ? b1[tid] : 0.f;
        b2s[tid] = (tid < 125) ? b2[tid] : 0.f;
    }
    if (tid < 16) b3s[tid] = (tid < OUT) ? b3[tid] : 0.f;
    if (DOBIN) {
        for (int idx = tid; idx < 300; idx += 256) {
            const int k = idx / 25, c = idx % 25;
            cbs[idx] = cb[k * 100 + c];
        }
    }
    __syncthreads();

    const int lane = tid & 31;     // row within tile
    const int w    = tid >> 5;     // column group 0..7
    const int j0   = w * 16;
    const int row  = blockIdx.x * 32 + lane;
    const bool valid = row < N_NODES;

    float xin[IN];
    #pragma unroll
    for (int k = 0; k < IN1; k++) xin[k] = valid ? xa[row * IN1 + k] : 0.f;
    #pragma unroll
    for (int k = 0; k < IN2; k++) xin[IN1 + k] = valid ? xb[row * IN2 + k] : 0.f;

    unsigned long long acc[8];

    // ---- layer 1 ----
    #pragma unroll
    for (int m = 0; m < 8; m++) acc[m] = pack2(b1s[j0 + 2 * m], b1s[j0 + 2 * m + 1]);
    #pragma unroll 4
    for (int k = 0; k < IN; k++) {
        const unsigned long long xx = pack2(xin[k], xin[k]);
        const ulonglong2* wp = (const ulonglong2*)(Ws1 + k * 128 + j0);
        const ulonglong2 wa = wp[0], wb = wp[1], wc = wp[2], wd = wp[3];
        acc[0] = ffma2(xx, wa.x, acc[0]); acc[1] = ffma2(xx, wa.y, acc[1]);
        acc[2] = ffma2(xx, wb.x, acc[2]); acc[3] = ffma2(xx, wb.y, acc[3]);
        acc[4] = ffma2(xx, wc.x, acc[4]); acc[5] = ffma2(xx, wc.y, acc[5]);
        acc[6] = ffma2(xx, wd.x, acc[6]); acc[7] = ffma2(xx, wd.y, acc[7]);
    }
    #pragma unroll
    for (int m = 0; m < 8; m++) {
        float a, b;
        unpack2(acc[m], a, b);
        h1s[lane * 133 + j0 + 2 * m]     = lrelu(a);
        h1s[lane * 133 + j0 + 2 * m + 1] = lrelu(b);
    }
    __syncthreads();

    // ---- layer 2 ----
    #pragma unroll
    for (int m = 0; m < 8; m++) acc[m] = pack2(b2s[j0 + 2 * m], b2s[j0 + 2 * m + 1]);
    #pragma unroll 5
    for (int k = 0; k < 125; k++) {
        const float hv = h1s[lane * 133 + k];
        const unsigned long long xx = pack2(hv, hv);
        const ulonglong2* wp = (const ulonglong2*)(Ws2 + k * 128 + j0);
        const ulonglong2 wa = wp[0], wb = wp[1], wc = wp[2], wd = wp[3];
        acc[0] = ffma2(xx, wa.x, acc[0]); acc[1] = ffma2(xx, wa.y, acc[1]);
        acc[2] = ffma2(xx, wb.x, acc[2]); acc[3] = ffma2(xx, wb.y, acc[3]);
        acc[4] = ffma2(xx, wc.x, acc[4]); acc[5] = ffma2(xx, wc.y, acc[5]);
        acc[6] = ffma2(xx, wd.x, acc[6]); acc[7] = ffma2(xx, wd.y, acc[7]);
    }
    #pragma unroll
    for (int m = 0; m < 8; m++) {
        float a, b;
        unpack2(acc[m], a, b);
        h2s[lane * 133 + j0 + 2 * m]     = lrelu(a);
        h2s[lane * 133 + j0 + 2 * m + 1] = lrelu(b);
    }
    __syncthreads();

    // ---- layer 3 ----
    float o1 = b3s[w], o2 = (OUT > 8) ? b3s[w + 8] : 0.f;
    #pragma unroll 5
    for (int k = 0; k < 125; k++) {
        const float hv = h2s[lane * 133 + k];
        o1 += hv * Ws3[k * 16 + w];
        if (OUT > 8) o2 += hv * Ws3[k * 16 + w + 8];
    }
    if (valid && w < OUT) out[row * OUT + w] = o1;
    if (OUT > 8 && valid && w + 8 < OUT) out[row * OUT + w + 8] = o2;

    if (DOBIN) {
        // stash full h row in smem (h1s is dead now), then per-row argmax bin
        float* Hrow = h1s;
        if (w < OUT) Hrow[lane * 13 + w] = o1;
        if (w < 4)   Hrow[lane * 13 + w + 8] = o2;
        __syncthreads();
        if (tid < 32) {
            const int r2 = blockIdx.x * 32 + tid;
            if (r2 < N_NODES) {
                float hr[12];
                #pragma unroll
                for (int k = 0; k < 12; k++) hr[k] = Hrow[tid * 13 + k];
                float mul[25];
                #pragma unroll
                for (int c = 0; c < 25; c++) {
                    float s = 0.f;
                    #pragma unroll
                    for (int k = 0; k < 12; k++) s += hr[k] * cbs[k * 25 + c];
                    mul[c] = s;
                }
                float best = -3.4e38f; int bi = 0;
                #pragma unroll
                for (int c = 0; c < 50; c++) {
                    const float v = (c < 25) ? mul[c] : -mul[c - 25];
                    if (v > best) { best = v; bi = c; }   // first-max: jnp.argmax
                }
                g_bin[r2] = bi;
            }
        }
    }
}

// ---------------- stable counting-sort, self-contained (no global hist) ----
// Block b = bin b. 8 warps, each owns a 625-element chunk. Position of node i
// with bin b = #(bin<b over all) + #(bin==b with index<i): exact stable argsort.
__global__ __launch_bounds__(256, 1) void sort_kernel()
{
    __shared__ int cB[8], cL[8];
    const int b = blockIdx.x;
    const int w = threadIdx.x >> 5, lane = threadIdx.x & 31;
    const int beg = w * 625, end = beg + 625;

    int nB = 0, nL = 0;
    for (int i0 = beg; i0 < end; i0 += 32) {
        const int i = i0 + lane;
        const bool inr = i < end;
        const int bv = inr ? g_bin[i] : 0x7fffffff;
        nB += __popc(__ballot_sync(0xffffffffu, inr && bv == b));
        nL += __popc(__ballot_sync(0xffffffffu, inr && bv <  b));
    }
    if (lane == 0) { cB[w] = nB; cL[w] = nL; }
    __syncthreads();

    int off = 0;
    #pragma unroll
    for (int q = 0; q < 8; q++) off += cL[q];
    for (int q = 0; q < w; q++) off += cB[q];

    for (int i0 = beg; i0 < end; i0 += 32) {
        const int i = i0 + lane;
        const bool inr = i < end;
        const int bv = inr ? g_bin[i] : 0x7fffffff;
        const bool p = inr && bv == b;
        const unsigned m = __ballot_sync(0xffffffffu, p);
        if (p) g_sorted[off + __popc(m & ((1u << lane) - 1u))] = i;
        off += __popc(m);
    }
}

// ---------------- per-chunk: similarity, top-16, GCNConv, GraphConv ----------
__global__ __launch_bounds__(512, 1)
void bin_kernel(const float* __restrict__ gcnW, const float* __restrict__ gcnb,
                const float* __restrict__ Wrel, const float* __restrict__ brel,
                const float* __restrict__ Wroot)
{
    extern __shared__ float sm[];
    float* P    = sm;                   // 100 x 13 (pre-leaky h, then leaky in place)
    float* D    = P + 1300;             // 100 x 101 sigmoid similarity
    float* HW   = D + 10100;            // 100 x 33
    float* GC   = HW + 3300;            // 100 x 33
    float* AGG  = GC + 3300;            // 100 x 33
    float* Ew   = AGG + 3300;           // 1600 edge weights
    float* coef = Ew + 1600;            // 1600 ew * dis[src]
    float* degf = coef + 1600;          // 100
    float* gws  = degf + 100;           // 384 gcnW
    float* gbs  = gws + 384;            // 32
    float* wrs  = gbs + 32;             // 1024 Wrel
    float* wts  = wrs + 1024;           // 1024 Wroot
    float* brs  = wts + 1024;           // 32
    int* sids  = (int*)(brs + 32);      // 100
    int* Ed    = sids + 100;            // 1600 local dst
    int* roff  = Ed + 1600;             // 128 (CSR offsets, scan scratch)
    int* cnt   = roff + 128;            // 100
    int* rlist = cnt + 100;             // 1600

    const int tid = threadIdx.x;
    const int b = blockIdx.x;

    if (tid < 100) sids[tid] = g_sorted[b * 100 + tid];
    for (int idx = tid; idx < 384; idx += 512) gws[idx] = gcnW[idx];
    for (int idx = tid; idx < 1024; idx += 512) { wrs[idx] = Wrel[idx]; wts[idx] = Wroot[idx]; }
    if (tid < 32) { gbs[tid] = gcnb[tid]; brs[tid] = brel[tid]; }
    if (tid < 128) roff[tid] = 0;
    if (tid < 100) cnt[tid] = 0;
    __syncthreads();
    for (int idx = tid; idx < 1200; idx += 512) {
        const int i = idx / 12, k = idx % 12;
        P[i * 13 + k] = g_h[sids[i] * 12 + k];
    }
    __syncthreads();

    // sigmoid similarity (symmetric upper triangle)
    for (int p = tid; p < 10000; p += 512) {
        const int i = p / 100, j = p % 100;
        if (j < i) continue;
        float s = 0.f;
        #pragma unroll
        for (int k = 0; k < 12; k++) s += P[i * 13 + k] * P[j * 13 + k];
        const float v = 1.f / (1.f + __expf(-s));
        D[i * 101 + j] = v;
        D[j * 101 + i] = v;
    }
    __syncthreads();

    // top-16 per row: register-resident streaming insertion (stable, lower index on tie)
    if (tid < 100) {
        const float* Drow = D + tid * 101;
        float tv[16]; int tj[16];
        #pragma unroll
        for (int s = 0; s < 16; s++) { tv[s] = -1.f; tj[s] = 0; }
        for (int j = 0; j < 100; j++) {
            const float v = Drow[j];
            if (v > tv[15]) {              // strict >: earlier index wins ties
                #pragma unroll
                for (int s = 15; s >= 1; s--) {
                    const bool up = (v > tv[s - 1]);
                    const bool here = !up && (v > tv[s]);
                    const float nv = up ? tv[s - 1] : (here ? v : tv[s]);
                    const int   nj = up ? tj[s - 1] : (here ? j : tj[s]);
                    tv[s] = nv; tj[s] = nj;
                }
                if (v > tv[0]) { tv[0] = v; tj[0] = 0 * tj[0] + 0; tj[0] = 0; tj[0] = 0; tj[0] = 0; tj[0] = 0; tj[0] = 0; tj[0] = 0; tj[0] = 0; tj[0] = j; }
            }
        }
        #pragma unroll
        for (int s = 0; s < 16; s++) { Ew[tid * 16 + s] = tv[s]; Ed[tid * 16 + s] = tj[s]; }
    }
    __syncthreads();

    // reverse CSR
    for (int e = tid; e < 1600; e += 512) atomicAdd(&roff[Ed[e] + 1], 1);
    __syncthreads();
    for (int d = 1; d < 128; d <<= 1) {           // block-wide inclusive scan of roff[0..100]
        int v = 0;
        if (tid < 101 && tid >= d) v = roff[tid - d];
        __syncthreads();
        if (tid < 101) roff[tid] += v;
        __syncthreads();
    }
    for (int e = tid; e < 1600; e += 512) {
        const int d = Ed[e];
        const int slot = atomicAdd(&cnt[d], 1);
        rlist[roff[d] + slot] = e;
    }
    __syncthreads();

    // degree (self loop 1 + incoming ew) -> deg^-0.5
    if (tid < 100) {
        float dg = 1.f;
        const int q1 = roff[tid + 1];
        for (int q = roff[tid]; q < q1; q++) dg += Ew[rlist[q]];
        degf[tid] = 1.f / sqrtf(dg);
    }
    __syncthreads();

    // leaky(h) in place, edge coefficients
    for (int idx = tid; idx < 1300; idx += 512) P[idx] = lrelu(P[idx]);
    for (int e = tid; e < 1600; e += 512) coef[e] = Ew[e] * degf[e >> 4];
    __syncthreads();

    const int f  = tid & 31;
    const int c0 = tid >> 5;     // 16 row groups

    // HW = leaky(h) @ gcnW
    for (int c = c0; c < 100; c += 16) {
        float a = 0.f;
        #pragma unroll
        for (int k = 0; k < 12; k++) a += P[c * 13 + k] * gws[k * 32 + f];
        HW[c * 33 + f] = a;
    }
    __syncthreads();

    // GCNConv
    for (int c = c0; c < 100; c += 16) {
        float a = 0.f;
        const int q1 = roff[c + 1];
        for (int q = roff[c]; q < q1; q++) {
            const int e = rlist[q];
            a += coef[e] * HW[(e >> 4) * 33 + f];
        }
        const float dc = degf[c];
        GC[c * 33 + f] = gbs[f] + dc * a + dc * dc * HW[c * 33 + f];
    }
    __syncthreads();

    // GraphConv aggregate
    for (int c = c0; c < 100; c += 16) {
        float a = 0.f;
        const int q1 = roff[c + 1];
        for (int q = roff[c]; q < q1; q++) {
            const int e = rlist[q];
            a += Ew[e] * GC[(e >> 4) * 33 + f];
        }
        AGG[c * 33 + f] = a;
    }
    __syncthreads();

    // AGG @ Wrel + brel + GC @ Wroot, leaky, scatter
    for (int c = c0; c < 100; c += 16) {
        float a = brs[f];
        #pragma unroll
        for (int k = 0; k < 32; k++) a += AGG[c * 33 + k] * wrs[k * 32 + f] + GC[c * 33 + k] * wts[k * 32 + f];
        g_hf[sids[c] * 32 + f] = lrelu(a);
    }
}

// ---------------- host launcher ------------------------------------------
static size_t mlp_smem_bytes(int IN, bool dobin) {
    return (size_t)(IN * 128 + 125 * 128 + 125 * 16 + 128 + 128 + 16 + 2 * 32 * 133 + (dobin ? 300 : 0)) * 4;
}
static size_t bin_smem_bytes() {
    size_t fl = 1300 + 10100 + 3 * 3300 + 1600 + 1600 + 100 + 384 + 32 + 1024 + 1024 + 32;
    size_t in = 100 + 1600 + 128 + 100 + 1600;
    return (fl + in) * 4;
}

extern "C" void kernel_launch(void* const* d_in, const int* in_sizes, int n_in,
                              void* d_out, int out_size)
{
    const float* x       = (const float*)d_in[0];
    const float* ygen_id = (const float*)d_in[1];
    const float* ygen    = (const float*)d_in[2];
    const float* cb      = (const float*)d_in[3];
    const float* nn1_W1 = (const float*)d_in[4];
    const float* nn1_b1 = (const float*)d_in[5];
    const float* nn1_W2 = (const float*)d_in[6];
    const float* nn1_b2 = (const float*)d_in[7];
    const float* nn1_W3 = (const float*)d_in[8];
    const float* nn1_b3 = (const float*)d_in[9];
    const float* gcn_W  = (const float*)d_in[10];
    const float* gcn_b  = (const float*)d_in[11];
    const float* gc_Wrel  = (const float*)d_in[12];
    const float* gc_brel  = (const float*)d_in[13];
    const float* gc_Wroot = (const float*)d_in[14];
    const float* nn2_W1 = (const float*)d_in[15];
    const float* nn2_b1 = (const float*)d_in[16];
    const float* nn2_W2 = (const float*)d_in[17];
    const float* nn2_b2 = (const float*)d_in[18];
    const float* nn2_W3 = (const float*)d_in[19];
    const float* nn2_b3 = (const float*)d_in[20];
    const float* nn3_W1 = (const float*)d_in[21];
    const float* nn3_b1 = (const float*)d_in[22];
    const float* nn3_W2 = (const float*)d_in[23];
    const float* nn3_b2 = (const float*)d_in[24];
    const float* nn3_W3 = (const float*)d_in[25];
    const float* nn3_b3 = (const float*)d_in[26];

    float* out = (float*)d_out;
    float* cand_ids = out;               // [5000,6]
    float* cand_p4  = out + 30000;       // [5000,6]

    void *ph, *phf;
    cudaGetSymbolAddress(&ph, g_h);
    cudaGetSymbolAddress(&phf, g_hf);
    float* h_ptr  = (float*)ph;
    float* hf_ptr = (float*)phf;

    cudaFuncSetAttribute(mlp_kernel<12, 0, 12, true>,  cudaFuncAttributeMaxDynamicSharedMemorySize, (int)mlp_smem_bytes(12, true));
    cudaFuncSetAttribute(mlp_kernel<32, 0, 6, false>,  cudaFuncAttributeMaxDynamicSharedMemorySize, (int)mlp_smem_bytes(32, false));
    cudaFuncSetAttribute(mlp_kernel<32, 6, 6, false>,  cudaFuncAttributeMaxDynamicSharedMemorySize, (int)mlp_smem_bytes(38, false));
    cudaFuncSetAttribute(bin_kernel, cudaFuncAttributeMaxDynamicSharedMemorySize, (int)bin_smem_bytes());

    const int grid = (N_NODES + 31) / 32;   // 157

    // 1) nn1 + fused LSH binning
    mlp_kernel<12, 0, 12, true><<<grid, 256, mlp_smem_bytes(12, true)>>>(
        x, nullptr, nn1_W1, nn1_b1, nn1_W2, nn1_b2, nn1_W3, nn1_b3,
        h_ptr, cb, nullptr, nullptr, 0);

    // 2) stable argsort by bin
    sort_kernel<<<NBINS, 256>>>();

    // 3) per-chunk graph build + GCN + GraphConv
    bin_kernel<<<NBINS, 512, bin_smem_bytes()>>>(gcn_W, gcn_b, gc_Wrel, gc_brel, gc_Wroot);

    // 4) nn2 (+ ygen_id passthrough)
    mlp_kernel<32, 0, 6, false><<<grid, 256, mlp_smem_bytes(32, false)>>>(
        hf_ptr, nullptr, nn2_W1, nn2_b1, nn2_W2, nn2_b2, nn2_W3, nn2_b3,
        cand_ids, nullptr, ygen_id, out + 60000, 30000);

    // 5) nn3 (+ ygen passthrough)
    mlp_kernel<32, 6, 6, false><<<grid, 256, mlp_smem_bytes(38, false)>>>(
        hf_ptr, cand_ids, nn3_W1, nn3_b1, nn3_W2, nn3_b2, nn3_W3, nn3_b3,
        cand_p4, nullptr, ygen, out + 90000, 30000);
}

// round 3
// speedup vs baseline: 3.4034x; 1.3814x over previous
#include <cuda_runtime.h>
#include <math.h>

#define N_NODES 5000
#define NBINS 50
#define KNN 16
#define SLOPE 0.01f

// ---------------- device scratch ----------------
__device__ float g_h[N_NODES * 12];     // nn1 output (pre-leaky)
__device__ int   g_bin[N_NODES];
__device__ int   g_sorted[N_NODES];     // stable argsort of g_bin
__device__ float g_hf[N_NODES * 32];    // post-conv, post-leaky features

__device__ __forceinline__ float lrelu(float v) { return v > 0.f ? v : SLOPE * v; }

__device__ __forceinline__ unsigned long long pack2(float a, float b) {
    unsigned long long r;
    asm("mov.b64 %0, {%1, %2};" : "=l"(r) : "r"(__float_as_uint(a)), "r"(__float_as_uint(b)));
    return r;
}
__device__ __forceinline__ void unpack2(unsigned long long p, float& a, float& b) {
    unsigned int x, y;
    asm("mov.b64 {%0, %1}, %2;" : "=r"(x), "=r"(y) : "l"(p));
    a = __uint_as_float(x); b = __uint_as_float(y);
}
__device__ __forceinline__ unsigned long long ffma2(unsigned long long a, unsigned long long b, unsigned long long c) {
    unsigned long long d;
    asm("fma.rn.f32x2 %0, %1, %2, %3;" : "=l"(d) : "l"(a), "l"(b), "l"(c));
    return d;
}

// ---------------- shared MLP building blocks -----------------------------
// Thread map (512 threads): warp w16 = tid>>5; colGroup cg = w16 & 7 (16 cols);
// warpRow wr = w16>>3 (2 row groups of 32); lane = row within group.
// Block covers 64 rows.

template <int IN, int OUT>
__device__ __forceinline__ void stage_net(
    const float* __restrict__ W1, const float* __restrict__ b1,
    const float* __restrict__ W2, const float* __restrict__ b2,
    const float* __restrict__ W3, const float* __restrict__ b3,
    float* Ws1, float* Ws2, float* Ws3, float* b1s, float* b2s, float* b3s, int tid)
{
    for (int idx = tid; idx < IN * 128; idx += 512) {
        const int k = idx >> 7, j = idx & 127;
        Ws1[idx] = (j < 125) ? W1[k * 125 + j] : 0.f;
    }
    for (int idx = tid; idx < 125 * 128; idx += 512) {
        const int k = idx >> 7, j = idx & 127;
        Ws2[idx] = (j < 125) ? W2[k * 125 + j] : 0.f;
    }
    for (int idx = tid; idx < 125 * 16; idx += 512) {
        const int k = idx >> 4, o = idx & 15;
        Ws3[idx] = (o < OUT) ? W3[k * OUT + o] : 0.f;
    }
    if (tid < 128) {
        b1s[tid] = (tid < 125) ? b1[tid] : 0.f;
        b2s[tid] = (tid < 125) ? b2[tid] : 0.f;
    } else if (tid < 144) {
        const int o = tid - 128;
        b3s[o] = (o < OUT) ? b3[o] : 0.f;
    }
}

template <int IN>
__device__ __forceinline__ void dense16_reg(const float* __restrict__ Ws, const float* __restrict__ xin,
                                            int j0, unsigned long long acc[8])
{
    #pragma unroll
    for (int k = 0; k < IN; k++) {
        const unsigned long long xx = pack2(xin[k], xin[k]);
        const ulonglong2* wp = (const ulonglong2*)(Ws + k * 128 + j0);
        const ulonglong2 wa = wp[0], wb = wp[1], wc = wp[2], wd = wp[3];
        acc[0] = ffma2(xx, wa.x, acc[0]); acc[1] = ffma2(xx, wa.y, acc[1]);
        acc[2] = ffma2(xx, wb.x, acc[2]); acc[3] = ffma2(xx, wb.y, acc[3]);
        acc[4] = ffma2(xx, wc.x, acc[4]); acc[5] = ffma2(xx, wc.y, acc[5]);
        acc[6] = ffma2(xx, wd.x, acc[6]); acc[7] = ffma2(xx, wd.y, acc[7]);
    }
}

__device__ __forceinline__ void dense16_smem(const float* __restrict__ Ws, const float* __restrict__ hrow,
                                             int j0, unsigned long long acc[8])
{
    #pragma unroll 5
    for (int k = 0; k < 125; k++) {
        const float hv = hrow[k];
        const unsigned long long xx = pack2(hv, hv);
        const ulonglong2* wp = (const ulonglong2*)(Ws + k * 128 + j0);
        const ulonglong2 wa = wp[0], wb = wp[1], wc = wp[2], wd = wp[3];
        acc[0] = ffma2(xx, wa.x, acc[0]); acc[1] = ffma2(xx, wa.y, acc[1]);
        acc[2] = ffma2(xx, wb.x, acc[2]); acc[3] = ffma2(xx, wb.y, acc[3]);
        acc[4] = ffma2(xx, wc.x, acc[4]); acc[5] = ffma2(xx, wc.y, acc[5]);
        acc[6] = ffma2(xx, wd.x, acc[6]); acc[7] = ffma2(xx, wd.y, acc[7]);
    }
}

// full 3-layer net: xin[IN] regs -> o1 (col cg), o2 (col cg+8)
template <int IN>
__device__ __forceinline__ void run_mlp(const float* __restrict__ xin,
                                        const float* Ws1, const float* Ws2, const float* Ws3,
                                        const float* b1s, const float* b2s, const float* b3s,
                                        float* hbuf, int lr, int j0, int cg,
                                        float& o1, float& o2)
{
    unsigned long long acc[8];
    float* hrow = hbuf + lr * 133;

    #pragma unroll
    for (int m = 0; m < 8; m++) acc[m] = pack2(b1s[j0 + 2 * m], b1s[j0 + 2 * m + 1]);
    dense16_reg<IN>(Ws1, xin, j0, acc);
    #pragma unroll
    for (int m = 0; m < 8; m++) {
        float a, b; unpack2(acc[m], a, b);
        hrow[j0 + 2 * m] = lrelu(a); hrow[j0 + 2 * m + 1] = lrelu(b);
    }
    __syncthreads();

    #pragma unroll
    for (int m = 0; m < 8; m++) acc[m] = pack2(b2s[j0 + 2 * m], b2s[j0 + 2 * m + 1]);
    dense16_smem(Ws2, hrow, j0, acc);
    __syncthreads();                       // all h1 reads complete
    #pragma unroll
    for (int m = 0; m < 8; m++) {
        float a, b; unpack2(acc[m], a, b);
        hrow[j0 + 2 * m] = lrelu(a); hrow[j0 + 2 * m + 1] = lrelu(b);
    }
    __syncthreads();

    o1 = b3s[cg]; o2 = b3s[cg + 8];
    #pragma unroll 5
    for (int k = 0; k < 125; k++) {
        const float hv = hrow[k];
        o1 += hv * Ws3[k * 16 + cg];
        o2 += hv * Ws3[k * 16 + cg + 8];
    }
}

// ---------------- nn1 + fused LSH binning --------------------------------
__global__ __launch_bounds__(512, 1)
void nn1_kernel(const float* __restrict__ x,
                const float* __restrict__ W1, const float* __restrict__ b1,
                const float* __restrict__ W2, const float* __restrict__ b2,
                const float* __restrict__ W3, const float* __restrict__ b3,
                const float* __restrict__ cb)
{
    extern __shared__ float sm[];
    float* Ws1 = sm;                      // 12*128
    float* Ws2 = Ws1 + 12 * 128;          // 125*128
    float* Ws3 = Ws2 + 125 * 128;         // 125*16
    float* b1s = Ws3 + 2000;              // 128
    float* b2s = b1s + 128;               // 128
    float* b3s = b2s + 128;               // 16
    float* hbuf = b3s + 16;               // 64*133
    float* cbs  = hbuf + 64 * 133;        // 300
    float* Hrow = cbs + 300;              // 64*13

    const int tid = threadIdx.x;
    stage_net<12, 12>(W1, b1, W2, b2, W3, b3, Ws1, Ws2, Ws3, b1s, b2s, b3s, tid);
    for (int idx = tid; idx < 300; idx += 512) {
        const int k = idx / 25, c = idx % 25;
        cbs[idx] = cb[k * 100 + c];
    }
    __syncthreads();

    const int lane = tid & 31;
    const int w16  = tid >> 5;
    const int cg   = w16 & 7;
    const int wr   = w16 >> 3;
    const int lr   = wr * 32 + lane;
    const int j0   = cg * 16;
    const int row  = blockIdx.x * 64 + lr;
    const bool valid = row < N_NODES;

    float xin[12];
    #pragma unroll
    for (int k = 0; k < 12; k++) xin[k] = valid ? x[row * 12 + k] : 0.f;

    float o1, o2;
    run_mlp<12>(xin, Ws1, Ws2, Ws3, b1s, b2s, b3s, hbuf, lr, j0, cg, o1, o2);

    if (valid) {
        g_h[row * 12 + cg] = o1;
        if (cg < 4) g_h[row * 12 + 8 + cg] = o2;
    }
    Hrow[lr * 13 + cg] = o1;
    if (cg < 4) Hrow[lr * 13 + 8 + cg] = o2;
    __syncthreads();

    if (tid < 64) {
        const int r2 = blockIdx.x * 64 + tid;
        if (r2 < N_NODES) {
            float hr[12];
            #pragma unroll
            for (int k = 0; k < 12; k++) hr[k] = Hrow[tid * 13 + k];
            float mul[25];
            #pragma unroll
            for (int c = 0; c < 25; c++) {
                float s = 0.f;
                #pragma unroll
                for (int k = 0; k < 12; k++) s += hr[k] * cbs[k * 25 + c];
                mul[c] = s;
            }
            float best = -3.4e38f; int bi = 0;
            #pragma unroll
            for (int c = 0; c < 50; c++) {
                const float v = (c < 25) ? mul[c] : -mul[c - 25];
                if (v > best) { best = v; bi = c; }   // first-max: jnp.argmax
            }
            g_bin[r2] = bi;
        }
    }
}

// ---------------- fused nn2 + nn3 (+ passthrough copies) ------------------
__global__ __launch_bounds__(512, 1)
void nn23_kernel(const float* __restrict__ A_W1, const float* __restrict__ A_b1,
                 const float* __restrict__ A_W2, const float* __restrict__ A_b2,
                 const float* __restrict__ A_W3, const float* __restrict__ A_b3,
                 const float* __restrict__ B_W1, const float* __restrict__ B_b1,
                 const float* __restrict__ B_W2, const float* __restrict__ B_b2,
                 const float* __restrict__ B_W3, const float* __restrict__ B_b3,
                 float* __restrict__ cand_ids, float* __restrict__ cand_p4,
                 const float* __restrict__ ygen_id, float* __restrict__ out_yid,
                 const float* __restrict__ ygen,    float* __restrict__ out_yg)
{
    extern __shared__ float sm[];
    float* AWs1 = sm;                     // 32*128
    float* AWs2 = AWs1 + 32 * 128;        // 125*128
    float* AWs3 = AWs2 + 16000;           // 125*16
    float* Ab1  = AWs3 + 2000;            // 128
    float* Ab2  = Ab1 + 128;
    float* Ab3  = Ab2 + 128;              // 16
    float* BWs1 = Ab3 + 16;               // 38*128
    float* BWs2 = BWs1 + 38 * 128;        // 125*128
    float* BWs3 = BWs2 + 16000;           // 125*16
    float* Bb1  = BWs3 + 2000;
    float* Bb2  = Bb1 + 128;
    float* Bb3  = Bb2 + 128;              // 16
    float* hbuf = Bb3 + 16;               // 64*133
    float* ids  = hbuf + 64 * 133;        // 64*8

    const int tid = threadIdx.x;
    const int gt  = blockIdx.x * 512 + tid;
    if (gt < 30000) { out_yid[gt] = ygen_id[gt]; out_yg[gt] = ygen[gt]; }

    stage_net<32, 6>(A_W1, A_b1, A_W2, A_b2, A_W3, A_b3, AWs1, AWs2, AWs3, Ab1, Ab2, Ab3, tid);
    stage_net<38, 6>(B_W1, B_b1, B_W2, B_b2, B_W3, B_b3, BWs1, BWs2, BWs3, Bb1, Bb2, Bb3, tid);
    __syncthreads();

    const int lane = tid & 31;
    const int w16  = tid >> 5;
    const int cg   = w16 & 7;
    const int wr   = w16 >> 3;
    const int lr   = wr * 32 + lane;
    const int j0   = cg * 16;
    const int row  = blockIdx.x * 64 + lr;
    const bool valid = row < N_NODES;

    float xin[38];
    #pragma unroll
    for (int k = 0; k < 32; k++) xin[k] = valid ? g_hf[row * 32 + k] : 0.f;

    float o1, o2;
    run_mlp<32>(xin, AWs1, AWs2, AWs3, Ab1, Ab2, Ab3, hbuf, lr, j0, cg, o1, o2);

    if (cg < 6) {
        if (valid) cand_ids[row * 6 + cg] = o1;
        ids[lr * 8 + cg] = o1;
    }
    __syncthreads();

    #pragma unroll
    for (int k = 0; k < 6; k++) xin[32 + k] = ids[lr * 8 + k];

    run_mlp<38>(xin, BWs1, BWs2, BWs3, Bb1, Bb2, Bb3, hbuf, lr, j0, cg, o1, o2);

    if (valid && cg < 6) cand_p4[row * 6 + cg] = o1;
}

// ---------------- stable counting-sort ------------------------------------
__global__ __launch_bounds__(256, 1) void sort_kernel()
{
    __shared__ int cB[8], cL[8];
    const int b = blockIdx.x;
    const int w = threadIdx.x >> 5, lane = threadIdx.x & 31;
    const int beg = w * 625, end = beg + 625;

    int nB = 0, nL = 0;
    for (int i0 = beg; i0 < end; i0 += 32) {
        const int i = i0 + lane;
        const bool inr = i < end;
        const int bv = inr ? g_bin[i] : 0x7fffffff;
        nB += __popc(__ballot_sync(0xffffffffu, inr && bv == b));
        nL += __popc(__ballot_sync(0xffffffffu, inr && bv <  b));
    }
    if (lane == 0) { cB[w] = nB; cL[w] = nL; }
    __syncthreads();

    int off = 0;
    #pragma unroll
    for (int q = 0; q < 8; q++) off += cL[q];
    for (int q = 0; q < w; q++) off += cB[q];

    for (int i0 = beg; i0 < end; i0 += 32) {
        const int i = i0 + lane;
        const bool inr = i < end;
        const int bv = inr ? g_bin[i] : 0x7fffffff;
        const bool p = inr && bv == b;
        const unsigned m = __ballot_sync(0xffffffffu, p);
        if (p) g_sorted[off + __popc(m & ((1u << lane) - 1u))] = i;
        off += __popc(m);
    }
}

// ---------------- per-chunk: similarity, top-16, GCNConv, GraphConv -------
__global__ __launch_bounds__(512, 1)
void bin_kernel(const float* __restrict__ gcnW, const float* __restrict__ gcnb,
                const float* __restrict__ Wrel, const float* __restrict__ brel,
                const float* __restrict__ Wroot)
{
    extern __shared__ float sm[];
    float* P    = sm;                   // 100 x 13
    float* D    = P + 1300;             // 100 x 101
    float* HW   = D + 10100;            // 100 x 33
    float* GC   = HW + 3300;
    float* AGG  = GC + 3300;
    float* Ew   = AGG + 3300;           // 1600
    float* coef = Ew + 1600;            // 1600
    float* degf = coef + 1600;          // 100
    float* gws  = degf + 100;           // 384
    float* gbs  = gws + 384;            // 32
    float* wrs  = gbs + 32;             // 1024
    float* wts  = wrs + 1024;           // 1024
    float* brs  = wts + 1024;           // 32
    int* sids  = (int*)(brs + 32);      // 100
    int* Ed    = sids + 100;            // 1600
    int* roff  = Ed + 1600;             // 128
    int* cnt   = roff + 128;            // 100
    int* rlist = cnt + 100;             // 1600

    const int tid = threadIdx.x;
    const int b = blockIdx.x;

    if (tid < 100) sids[tid] = g_sorted[b * 100 + tid];
    for (int idx = tid; idx < 384; idx += 512) gws[idx] = gcnW[idx];
    for (int idx = tid; idx < 1024; idx += 512) { wrs[idx] = Wrel[idx]; wts[idx] = Wroot[idx]; }
    if (tid < 32) { gbs[tid] = gcnb[tid]; brs[tid] = brel[tid]; }
    if (tid < 128) roff[tid] = 0;
    if (tid < 100) cnt[tid] = 0;
    __syncthreads();
    for (int idx = tid; idx < 1200; idx += 512) {
        const int i = idx / 12, k = idx % 12;
        P[i * 13 + k] = g_h[sids[i] * 12 + k];
    }
    __syncthreads();

    for (int p = tid; p < 10000; p += 512) {
        const int i = p / 100, j = p % 100;
        if (j < i) continue;
        float s = 0.f;
        #pragma unroll
        for (int k = 0; k < 12; k++) s += P[i * 13 + k] * P[j * 13 + k];
        const float v = 1.f / (1.f + __expf(-s));
        D[i * 101 + j] = v;
        D[j * 101 + i] = v;
    }
    __syncthreads();

    // top-16 per row: streaming insertion (stable: strict >, earlier index wins ties)
    if (tid < 100) {
        const float* Drow = D + tid * 101;
        float tv[16]; int tj[16];
        #pragma unroll
        for (int s = 0; s < 16; s++) { tv[s] = -1.f; tj[s] = 0; }
        for (int j = 0; j < 100; j++) {
            const float v = Drow[j];
            if (v > tv[15]) {
                #pragma unroll
                for (int s = 15; s >= 1; s--) {
                    const bool up = (v > tv[s - 1]);
                    const bool here = !up && (v > tv[s]);
                    tv[s] = up ? tv[s - 1] : (here ? v : tv[s]);
                    tj[s] = up ? tj[s - 1] : (here ? j : tj[s]);
                }
                if (v > tv[0]) { tv[0] = v; tj[0] = j; }
            }
        }
        #pragma unroll
        for (int s = 0; s < 16; s++) { Ew[tid * 16 + s] = tv[s]; Ed[tid * 16 + s] = tj[s]; }
    }
    __syncthreads();

    for (int e = tid; e < 1600; e += 512) atomicAdd(&roff[Ed[e] + 1], 1);
    __syncthreads();
    for (int d = 1; d < 128; d <<= 1) {
        int v = 0;
        if (tid < 101 && tid >= d) v = roff[tid - d];
        __syncthreads();
        if (tid < 101) roff[tid] += v;
        __syncthreads();
    }
    for (int e = tid; e < 1600; e += 512) {
        const int d = Ed[e];
        const int slot = atomicAdd(&cnt[d], 1);
        rlist[roff[d] + slot] = e;
    }
    __syncthreads();

    if (tid < 100) {
        float dg = 1.f;
        const int q1 = roff[tid + 1];
        for (int q = roff[tid]; q < q1; q++) dg += Ew[rlist[q]];
        degf[tid] = 1.f / sqrtf(dg);
    }
    __syncthreads();

    for (int idx = tid; idx < 1300; idx += 512) P[idx] = lrelu(P[idx]);
    for (int e = tid; e < 1600; e += 512) coef[e] = Ew[e] * degf[e >> 4];
    __syncthreads();

    const int f  = tid & 31;
    const int c0 = tid >> 5;

    for (int c = c0; c < 100; c += 16) {
        float a = 0.f;
        #pragma unroll
        for (int k = 0; k < 12; k++) a += P[c * 13 + k] * gws[k * 32 + f];
        HW[c * 33 + f] = a;
    }
    __syncthreads();

    for (int c = c0; c < 100; c += 16) {
        float a = 0.f;
        const int q1 = roff[c + 1];
        for (int q = roff[c]; q < q1; q++) {
            const int e = rlist[q];
            a += coef[e] * HW[(e >> 4) * 33 + f];
        }
        const float dc = degf[c];
        GC[c * 33 + f] = gbs[f] + dc * a + dc * dc * HW[c * 33 + f];
    }
    __syncthreads();

    for (int c = c0; c < 100; c += 16) {
        float a = 0.f;
        const int q1 = roff[c + 1];
        for (int q = roff[c]; q < q1; q++) {
            const int e = rlist[q];
            a += Ew[e] * GC[(e >> 4) * 33 + f];
        }
        AGG[c * 33 + f] = a;
    }
    __syncthreads();

    for (int c = c0; c < 100; c += 16) {
        float a = brs[f];
        #pragma unroll
        for (int k = 0; k < 32; k++) a += AGG[c * 33 + k] * wrs[k * 32 + f] + GC[c * 33 + k] * wts[k * 32 + f];
        g_hf[sids[c] * 32 + f] = lrelu(a);
    }
}

// ---------------- host launcher ------------------------------------------
static size_t nn1_smem() {
    return (size_t)(12 * 128 + 16000 + 2000 + 272 + 64 * 133 + 300 + 64 * 13) * 4;
}
static size_t nn23_smem() {
    return (size_t)((32 * 128 + 16000 + 2000 + 272) + (38 * 128 + 16000 + 2000 + 272) + 64 * 133 + 64 * 8) * 4;
}
static size_t bin_smem() {
    size_t fl = 1300 + 10100 + 3 * 3300 + 1600 + 1600 + 100 + 384 + 32 + 1024 + 1024 + 32;
    size_t in = 100 + 1600 + 128 + 100 + 1600;
    return (fl + in) * 4;
}

extern "C" void kernel_launch(void* const* d_in, const int* in_sizes, int n_in,
                              void* d_out, int out_size)
{
    const float* x       = (const float*)d_in[0];
    const float* ygen_id = (const float*)d_in[1];
    const float* ygen    = (const float*)d_in[2];
    const float* cb      = (const float*)d_in[3];
    const float* nn1_W1 = (const float*)d_in[4];
    const float* nn1_b1 = (const float*)d_in[5];
    const float* nn1_W2 = (const float*)d_in[6];
    const float* nn1_b2 = (const float*)d_in[7];
    const float* nn1_W3 = (const float*)d_in[8];
    const float* nn1_b3 = (const float*)d_in[9];
    const float* gcn_W  = (const float*)d_in[10];
    const float* gcn_b  = (const float*)d_in[11];
    const float* gc_Wrel  = (const float*)d_in[12];
    const float* gc_brel  = (const float*)d_in[13];
    const float* gc_Wroot = (const float*)d_in[14];
    const float* nn2_W1 = (const float*)d_in[15];
    const float* nn2_b1 = (const float*)d_in[16];
    const float* nn2_W2 = (const float*)d_in[17];
    const float* nn2_b2 = (const float*)d_in[18];
    const float* nn2_W3 = (const float*)d_in[19];
    const float* nn2_b3 = (const float*)d_in[20];
    const float* nn3_W1 = (const float*)d_in[21];
    const float* nn3_b1 = (const float*)d_in[22];
    const float* nn3_W2 = (const float*)d_in[23];
    const float* nn3_b2 = (const float*)d_in[24];
    const float* nn3_W3 = (const float*)d_in[25];
    const float* nn3_b3 = (const float*)d_in[26];

    float* out = (float*)d_out;

    cudaFuncSetAttribute(nn1_kernel,  cudaFuncAttributeMaxDynamicSharedMemorySize, (int)nn1_smem());
    cudaFuncSetAttribute(nn23_kernel, cudaFuncAttributeMaxDynamicSharedMemorySize, (int)nn23_smem());
    cudaFuncSetAttribute(bin_kernel,  cudaFuncAttributeMaxDynamicSharedMemorySize, (int)bin_smem());

    const int grid = (N_NODES + 63) / 64;   // 79

    nn1_kernel<<<grid, 512, nn1_smem()>>>(x, nn1_W1, nn1_b1, nn1_W2, nn1_b2, nn1_W3, nn1_b3, cb);
    sort_kernel<<<NBINS, 256>>>();
    bin_kernel<<<NBINS, 512, bin_smem()>>>(gcn_W, gcn_b, gc_Wrel, gc_brel, gc_Wroot);
    nn23_kernel<<<grid, 512, nn23_smem()>>>(
        nn2_W1, nn2_b1, nn2_W2, nn2_b2, nn2_W3, nn2_b3,
        nn3_W1, nn3_b1, nn3_W2, nn3_b2, nn3_W3, nn3_b3,
        out, out + 30000,
        ygen_id, out + 60000,
        ygen,    out + 90000);
}